// round 10
// baseline (speedup 1.0000x reference)
#include <cuda_runtime.h>
#include <cstdint>

#define BB      1024
#define MAXLEN  200
#define FF      64
#define DD      64
#define NT      256
#define GRID    304                        // 2 CTAs/SM x 152 SMs, persistent
#define RPW     25                         // rows per warp
#define KUNITS  3200                       // 16B units per k tile
#define KT      (MAXLEN * DD)              // 12800 floats per k tile
#define SMEM_FLOATS (2 * KT + 16 * DD + DD + DD + DD + 16)
#define SMEM_BYTES  (SMEM_FLOATS * 4)      // 107,328 B

__device__ __forceinline__ void cp_async16(uint32_t saddr, const void* gaddr) {
    asm volatile("cp.async.cg.shared.global [%0], [%1], 16;" :: "r"(saddr), "l"(gaddr) : "memory");
}
__device__ __forceinline__ void cp_commit() {
    asm volatile("cp.async.commit_group;" ::: "memory");
}
template<int N> __device__ __forceinline__ void cp_wait() {
    asm volatile("cp.async.wait_group %0;" :: "n"(N) : "memory");
}
__device__ __forceinline__ float fast_sigmoid(float x) {
    float t;
    asm("tanh.approx.f32 %0, %1;" : "=f"(t) : "f"(0.5f * x));
    return fmaf(0.5f, t, 0.5f);
}
__device__ __forceinline__ float fast_exp8(float x) {   // exp(x/8)
    float e;
    asm("ex2.approx.f32 %0, %1;" : "=f"(e) : "f"(x * 0.18033688011112042f));
    return e;
}
__device__ __forceinline__ void stage_k(uint32_t sbk, const float* kb, int tid) {
    const char* gk = (const char*)kb;
#pragma unroll
    for (int r = 0; r < 12; ++r) {
        int u = tid + r * NT;
        cp_async16(sbk + u * 16, gk + (size_t)u * 16);
    }
    if (tid < KUNITS - 12 * NT)
        cp_async16(sbk + (tid + 12 * NT) * 16, gk + (size_t)(tid + 12 * NT) * 16);
    cp_commit();
}

__global__ __launch_bounds__(NT, 2)
void fused_kernel(const float* __restrict__ q,
                  const float* __restrict__ k,
                  const int*   __restrict__ kes_length,
                  const float* __restrict__ fs,
                  const float* __restrict__ bias,
                  const float* __restrict__ Wq,
                  const float* __restrict__ Wk,
                  const float* __restrict__ Wv,
                  float*       __restrict__ out) {
    extern __shared__ float smd[];
    float* kb0   = smd;                    // k tile buffer 0
    float* kb1   = smd + KT;               // k tile buffer 1
    float* spart = smd + 2 * KT;           // 16*64 partials
    float* squ   = spart + 16 * DD;        // qbar
    float* stmp  = squ + DD;               // qbar @ Wq
    float* su    = stmp + DD;              // u, then w
    float* swr   = su + DD;                // 16 exp-sums

    const int tid  = threadIdx.x;
    const int lane = tid & 31;
    const int warp = tid >> 5;
    const int half = lane >> 4;
    const int hw   = tid >> 4;
    const int l16  = tid & 15;

    const float biasD = bias[0] * (float)DD;
    const uint32_t sb0 = (uint32_t)__cvta_generic_to_shared(kb0);
    const uint32_t sb1 = (uint32_t)__cvta_generic_to_shared(kb1);

    const int b0 = blockIdx.x;
    stage_k(sb0, k + (size_t)b0 * KT, tid);     // prime the pipeline

    int j = 0;
    for (int b = b0; b < BB; b += GRID, ++j) {
        const int bn = b + GRID;
        // ---- issue NEXT batch's k-DMA into the spare buffer ----
        if (bn < BB)
            stage_k((j & 1) ? sb0 : sb1, k + (size_t)bn * KT, tid);

        // ---- u-compute for batch b (runs in the DMA shadow) ----
        // qbar[d] = sum_f fs[f] * q[b,f,d]
        {
            const float4* qb4 = (const float4*)(q + (size_t)b * FF * DD);
            float4 a = make_float4(0.f, 0.f, 0.f, 0.f);
#pragma unroll
            for (int fi = 0; fi < 4; ++fi) {
                int f = hw + 16 * fi;
                float s = fs[f];
                float4 v = qb4[f * 16 + l16];
                a.x += s * v.x; a.y += s * v.y; a.z += s * v.z; a.w += s * v.w;
            }
            ((float4*)spart)[hw * 16 + l16] = a;
        }
        __syncthreads();
        if (tid < DD) {
            float s = 0.f;
#pragma unroll
            for (int i = 0; i < 16; ++i) s += spart[i * DD + tid];
            squ[tid] = s;
        }
        __syncthreads();
        // tmp[e] = sum_c qbar[c] * Wq[c,e]
        {
            float4 a = make_float4(0.f, 0.f, 0.f, 0.f);
#pragma unroll
            for (int ci = 0; ci < 4; ++ci) {
                int c = hw * 4 + ci;
                float s = squ[c];
                float4 v = ((const float4*)Wq)[c * 16 + l16];
                a.x += s * v.x; a.y += s * v.y; a.z += s * v.z; a.w += s * v.w;
            }
            ((float4*)spart)[hw * 16 + l16] = a;
        }
        __syncthreads();
        if (tid < DD) {
            float s = 0.f;
#pragma unroll
            for (int i = 0; i < 16; ++i) s += spart[i * DD + tid];
            stmp[tid] = s;
        }
        __syncthreads();
        // u[row] = sum_e tmp[e] * Wk[row,e]
        {
            float4 tv = ((const float4*)stmp)[l16];
#pragma unroll
            for (int r = 0; r < 4; ++r) {
                int row = hw + 16 * r;
                float4 wv = ((const float4*)(Wk + row * DD))[l16];
                float p = wv.x * tv.x + wv.y * tv.y + wv.z * tv.z + wv.w * tv.w;
#pragma unroll
                for (int o = 8; o; o >>= 1)
                    p += __shfl_xor_sync(0xffffffffu, p, o);
                if (l16 == 0) su[row] = p;
            }
        }

        // ---- wait for THIS batch's k tile (next batch keeps streaming) ----
        if (bn < BB) cp_wait<1>(); else cp_wait<0>();
        __syncthreads();

        const int   len   = kes_length[b];
        const float mfill = (len == 0) ? 1.f : 0.f;
        const float4 uv   = ((const float4*)su)[l16];
        const float4* kb4 = (const float4*)((j & 1) ? kb1 : kb0);
        const int rbase   = warp * RPW;

        float4 wa   = make_float4(0.f, 0.f, 0.f, 0.f);
        float  esum = 0.f;

#pragma unroll
        for (int i = 0; i < 13; ++i) {
            int  rl    = 2 * i + half;             // 0..25 ; 25 invalid
            bool valid = (rl < RPW);
            int  r     = rbase + (valid ? rl : 0);
            float4 kv  = kb4[r * 16 + l16];
            float pd = kv.x * uv.x + kv.y * uv.y + kv.z * uv.z + kv.w * uv.w;
#pragma unroll
            for (int o = 8; o; o >>= 1)
                pd += __shfl_xor_sync(0xffffffffu, pd, o);
            float e = 0.f;
            if (valid)
                e = (rbase + rl < len) ? fast_exp8(fast_sigmoid(pd + biasD)) : mfill;
            wa.x += e * kv.x; wa.y += e * kv.y;
            wa.z += e * kv.z; wa.w += e * kv.w;
            esum += e;
        }

        ((float4*)spart)[hw * 16 + l16] = wa;
        if (l16 == 0) swr[hw] = esum;
        __syncthreads();

        if (tid < DD) {
            float s = 0.f;
#pragma unroll
            for (int i = 0; i < 16; ++i) s += spart[i * DD + tid];
            su[tid] = s;
        }
        __syncthreads();

        // out[b,e] = inv * sum_c w[c] * Wv[c,e]
        {
            float4 a = make_float4(0.f, 0.f, 0.f, 0.f);
#pragma unroll
            for (int ci = 0; ci < 4; ++ci) {
                int c = hw * 4 + ci;
                float s = su[c];
                float4 v = ((const float4*)Wv)[c * 16 + l16];
                a.x += s * v.x; a.y += s * v.y; a.z += s * v.z; a.w += s * v.w;
            }
            ((float4*)spart)[hw * 16 + l16] = a;
        }
        __syncthreads();
        if (tid < DD) {
            float tot = 0.f;
#pragma unroll
            for (int i = 0; i < 16; ++i) tot += swr[i];
            float s = 0.f;
#pragma unroll
            for (int i = 0; i < 16; ++i) s += spart[i * DD + tid];
            out[(size_t)b * DD + tid] = s * (1.f / tot);
        }
        __syncthreads();   // protect spart/swr before next iteration reuses them
    }
}

extern "C" void kernel_launch(void* const* d_in, const int* in_sizes, int n_in,
                              void* d_out, int out_size) {
    const float* q    = (const float*)d_in[0];
    const float* k    = (const float*)d_in[1];
    // d_in[2] = v : unused by the reference computation
    const int*   kes  = (const int*)  d_in[3];
    const float* fs   = (const float*)d_in[4];
    const float* bias = (const float*)d_in[5];
    const float* Wq   = (const float*)d_in[6];
    const float* Wk   = (const float*)d_in[7];
    const float* Wv   = (const float*)d_in[8];
    float*       out  = (float*)d_out;

    cudaFuncSetAttribute(fused_kernel, cudaFuncAttributePreferredSharedMemoryCarveout, 100);
    cudaFuncSetAttribute(fused_kernel, cudaFuncAttributeMaxDynamicSharedMemorySize, SMEM_BYTES);
    fused_kernel<<<GRID, NT, SMEM_BYTES>>>(q, k, kes, fs, bias, Wq, Wk, Wv, out);
}

// round 11
// speedup vs baseline: 1.1085x; 1.1085x over previous
#include <cuda_runtime.h>
#include <cstdint>

#define BB      1024
#define MAXLEN  200
#define FF      64
#define DD      64
#define NT      256
#define RPW     25                         // rows per warp (weighted phase)
#define KUNITS  3200                       // 16B units per k tile
#define KT      (MAXLEN * DD)              // 12800 floats
#define SMEM2_FLOATS (KT + MAXLEN + 16 * DD + DD + DD + 16)
#define SMEM2_BYTES  (SMEM2_FLOATS * 4)    // 56,672 B -> 4 CTAs/SM

__device__ float g_u[BB * DD];             // 256 KB scratch: u per batch

__device__ __forceinline__ void cp_async16(uint32_t saddr, const void* gaddr) {
    asm volatile("cp.async.cg.shared.global [%0], [%1], 16;" :: "r"(saddr), "l"(gaddr) : "memory");
}
__device__ __forceinline__ void cp_commit() {
    asm volatile("cp.async.commit_group;" ::: "memory");
}
__device__ __forceinline__ void cp_wait_all() {
    asm volatile("cp.async.wait_group 0;" ::: "memory");
}
__device__ __forceinline__ float fast_sigmoid(float x) {
    float t;
    asm("tanh.approx.f32 %0, %1;" : "=f"(t) : "f"(0.5f * x));
    return fmaf(0.5f, t, 0.5f);
}
__device__ __forceinline__ float fast_exp8(float x) {   // exp(x/8)
    float e;
    asm("ex2.approx.f32 %0, %1;" : "=f"(e) : "f"(x * 0.18033688011112042f));
    return e;
}

// ================= Kernel 1: u[b] = ((fs.q[b]) @ Wq) @ Wk^T =================
__global__ __launch_bounds__(NT, 8)
void u_kernel(const float* __restrict__ q,
              const float* __restrict__ fs,
              const float* __restrict__ Wq,
              const float* __restrict__ Wk) {
    __shared__ float spart[16 * DD];
    __shared__ float squ[DD];
    __shared__ float stmp[DD];

    const int b   = blockIdx.x;
    const int tid = threadIdx.x;
    const int hw  = tid >> 4;
    const int l16 = tid & 15;

    // qbar[d] = sum_f fs[f] * q[b,f,d]
    {
        const float4* qb4 = (const float4*)(q + (size_t)b * FF * DD);
        float4 a = make_float4(0.f, 0.f, 0.f, 0.f);
#pragma unroll
        for (int fi = 0; fi < 4; ++fi) {
            int f = hw + 16 * fi;
            float s = fs[f];
            float4 v = qb4[f * 16 + l16];
            a.x += s * v.x; a.y += s * v.y; a.z += s * v.z; a.w += s * v.w;
        }
        ((float4*)spart)[hw * 16 + l16] = a;
    }
    __syncthreads();
    if (tid < DD) {
        float s = 0.f;
#pragma unroll
        for (int i = 0; i < 16; ++i) s += spart[i * DD + tid];
        squ[tid] = s;
    }
    __syncthreads();

    // tmp[e] = sum_c qbar[c] * Wq[c,e]
    {
        float4 a = make_float4(0.f, 0.f, 0.f, 0.f);
#pragma unroll
        for (int ci = 0; ci < 4; ++ci) {
            int c = hw * 4 + ci;
            float s = squ[c];
            float4 v = ((const float4*)Wq)[c * 16 + l16];
            a.x += s * v.x; a.y += s * v.y; a.z += s * v.z; a.w += s * v.w;
        }
        ((float4*)spart)[hw * 16 + l16] = a;
    }
    __syncthreads();
    if (tid < DD) {
        float s = 0.f;
#pragma unroll
        for (int i = 0; i < 16; ++i) s += spart[i * DD + tid];
        stmp[tid] = s;
    }
    __syncthreads();

    // u[row] = sum_e tmp[e] * Wk[row,e]
    {
        float4 tv = ((const float4*)stmp)[l16];
#pragma unroll
        for (int r = 0; r < 4; ++r) {
            int row = hw + 16 * r;
            float4 wv = ((const float4*)(Wk + row * DD))[l16];
            float p = wv.x * tv.x + wv.y * tv.y + wv.z * tv.z + wv.w * tv.w;
#pragma unroll
            for (int o = 8; o; o >>= 1)
                p += __shfl_xor_sync(0xffffffffu, p, o);
            if (l16 == 0) g_u[b * DD + row] = p;
        }
    }
}

// ======== Kernel 2: swizzled k staging + shuffle-free score/weighted-sum ========
// Swizzle: logical element (t, jg) [jg = float4 group 0..15] is stored at
// word offset t*64 + ((jg + t) & 15) * 4.  Conflict-free for BOTH
// thread-per-row access (score) and half-warp-per-row access (weighted sum).
__global__ __launch_bounds__(NT, 4)
void score_kernel(const float* __restrict__ k,
                  const int*   __restrict__ kes_length,
                  const float* __restrict__ bias,
                  const float* __restrict__ Wv,
                  float*       __restrict__ out) {
    extern __shared__ float smd[];
    float* kbuf  = smd;                    // 12800 floats, swizzled k tile
    float* sa    = kbuf + KT;              // 200 : e values
    float* spart = sa + MAXLEN;            // 16*64 partials
    float* su    = spart + 16 * DD;        // w
    float* sub   = su + DD;                // u (staged from g_u)
    float* swr   = sub + DD;               // 16 exp-sums

    const int b    = blockIdx.x;
    const int tid  = threadIdx.x;
    const int lane = tid & 31;
    const int warp = tid >> 5;
    const int half = lane >> 4;
    const int hw   = tid >> 4;
    const int l16  = tid & 15;

    // ---- bulk swizzled DMA: entire k[b], one commit group ----
    {
        const uint32_t sbk = (uint32_t)__cvta_generic_to_shared(kbuf);
        const char* gk = (const char*)(k + (size_t)b * KT);
#pragma unroll
        for (int r = 0; r < 12; ++r) {
            int uu = tid + r * NT;
            int t  = uu >> 4, jg = uu & 15;
            uint32_t dst = (uint32_t)(((t << 4) + ((jg + t) & 15)) << 4);
            cp_async16(sbk + dst, gk + (size_t)uu * 16);
        }
        if (tid < KUNITS - 12 * NT) {
            int uu = tid + 12 * NT;
            int t  = uu >> 4, jg = uu & 15;
            uint32_t dst = (uint32_t)(((t << 4) + ((jg + t) & 15)) << 4);
            cp_async16(sbk + dst, gk + (size_t)uu * 16);
        }
        cp_commit();
    }

    // stage u (L2-resident, tiny) into smem
    if (tid < 16)
        ((float4*)sub)[tid] = ((const float4*)(g_u + (size_t)b * DD))[tid];

    const int   len   = kes_length[b];
    const float biasD = bias[0] * (float)DD;
    const float mfill = (len == 0) ? 1.f : 0.f;

    cp_wait_all();
    __syncthreads();

    // ---- score phase: thread-per-row, zero shuffles ----
    if (tid < MAXLEN) {
        float p0 = 0.f, p1 = 0.f, p2 = 0.f, p3 = 0.f;
        const int base = tid * 64;
#pragma unroll
        for (int jg = 0; jg < 16; ++jg) {
            float4 kv = *(const float4*)(kbuf + base + (((jg + tid) & 15) << 2));
            float4 uv = *(const float4*)(sub + (jg << 2));   // broadcast
            p0 += kv.x * uv.x; p1 += kv.y * uv.y;
            p2 += kv.z * uv.z; p3 += kv.w * uv.w;
        }
        float p = (p0 + p1) + (p2 + p3);
        sa[tid] = (tid < len) ? fast_exp8(fast_sigmoid(p + biasD)) : mfill;
    }
    __syncthreads();

    // ---- weighted phase: half-warp per row, zero shuffles ----
    const int rbase = warp * RPW;
    float4 wa   = make_float4(0.f, 0.f, 0.f, 0.f);
    float  esum = 0.f;
#pragma unroll
    for (int i = 0; i < 13; ++i) {
        int  rl    = 2 * i + half;             // 0..25 ; 25 invalid
        bool valid = (rl < RPW);
        int  r     = rbase + (valid ? rl : 0);
        float4 kv  = *(const float4*)(kbuf + r * 64 + (((l16 + r) & 15) << 2));
        float  e   = valid ? sa[r] : 0.f;      // broadcast
        wa.x += e * kv.x; wa.y += e * kv.y;
        wa.z += e * kv.z; wa.w += e * kv.w;
        esum += e;
    }

    ((float4*)spart)[hw * 16 + l16] = wa;
    if (l16 == 0) swr[hw] = esum;
    __syncthreads();

    if (tid < DD) {
        float s = 0.f;
#pragma unroll
        for (int i = 0; i < 16; ++i) s += spart[i * DD + tid];
        su[tid] = s;
    }
    __syncthreads();

    // ---- out[b,e] = inv * sum_c w[c] * Wv[c,e] ----
    {
        float4 a = make_float4(0.f, 0.f, 0.f, 0.f);
#pragma unroll
        for (int ci = 0; ci < 4; ++ci) {
            int c = hw * 4 + ci;
            float s = su[c];
            float4 v = ((const float4*)Wv)[c * 16 + l16];
            a.x += s * v.x; a.y += s * v.y; a.z += s * v.z; a.w += s * v.w;
        }
        ((float4*)spart)[hw * 16 + l16] = a;
    }
    __syncthreads();
    if (tid < DD) {
        float tot = 0.f;
#pragma unroll
        for (int i = 0; i < 16; ++i) tot += swr[i];
        float s = 0.f;
#pragma unroll
        for (int i = 0; i < 16; ++i) s += spart[i * DD + tid];
        out[(size_t)b * DD + tid] = s * (1.f / tot);
    }
}

extern "C" void kernel_launch(void* const* d_in, const int* in_sizes, int n_in,
                              void* d_out, int out_size) {
    const float* q    = (const float*)d_in[0];
    const float* k    = (const float*)d_in[1];
    // d_in[2] = v : unused by the reference computation
    const int*   kes  = (const int*)  d_in[3];
    const float* fs   = (const float*)d_in[4];
    const float* bias = (const float*)d_in[5];
    const float* Wq   = (const float*)d_in[6];
    const float* Wk   = (const float*)d_in[7];
    const float* Wv   = (const float*)d_in[8];
    float*       out  = (float*)d_out;

    cudaFuncSetAttribute(score_kernel, cudaFuncAttributePreferredSharedMemoryCarveout, 100);
    cudaFuncSetAttribute(score_kernel, cudaFuncAttributeMaxDynamicSharedMemorySize, SMEM2_BYTES);

    u_kernel<<<BB, NT>>>(q, fs, Wq, Wk);
    score_kernel<<<BB, NT, SMEM2_BYTES>>>(k, kes, bias, Wv, out);
}

// round 12
// speedup vs baseline: 1.1235x; 1.0135x over previous
#include <cuda_runtime.h>
#include <cstdint>

#define BB      1024
#define MAXLEN  200
#define FF      64
#define DD      64
#define NT      256
#define CH      50                         // rows per chunk
#define KT      (MAXLEN * DD)              // 12800 floats
#define CHU     ((CH * DD * 4) / 16)       // 800 16B units per chunk
#define SMEM2_FLOATS (KT + 16 * DD + DD + DD + 16)
#define SMEM2_BYTES  (SMEM2_FLOATS * 4)    // 55,872 B -> 4 CTAs/SM

__device__ float g_u[BB * DD];             // 256 KB scratch: u per batch

__device__ __forceinline__ void cp_async16(uint32_t saddr, const void* gaddr) {
    asm volatile("cp.async.cg.shared.global [%0], [%1], 16;" :: "r"(saddr), "l"(gaddr) : "memory");
}
__device__ __forceinline__ void cp_commit() {
    asm volatile("cp.async.commit_group;" ::: "memory");
}
template<int N> __device__ __forceinline__ void cp_wait() {
    asm volatile("cp.async.wait_group %0;" :: "n"(N) : "memory");
}
__device__ __forceinline__ float fast_sigmoid(float x) {
    float t;
    asm("tanh.approx.f32 %0, %1;" : "=f"(t) : "f"(0.5f * x));
    return fmaf(0.5f, t, 0.5f);
}
__device__ __forceinline__ float fast_exp8(float x) {   // exp(x/8)
    float e;
    asm("ex2.approx.f32 %0, %1;" : "=f"(e) : "f"(x * 0.18033688011112042f));
    return e;
}

// ================= Kernel 1: u[b] = ((fs.q[b]) @ Wq) @ Wk^T =================
__global__ __launch_bounds__(NT, 8)
void u_kernel(const float* __restrict__ q,
              const float* __restrict__ fs,
              const float* __restrict__ Wq,
              const float* __restrict__ Wk) {
    __shared__ float spart[16 * DD];
    __shared__ float squ[DD];
    __shared__ float stmp[DD];

    const int b   = blockIdx.x;
    const int tid = threadIdx.x;
    const int hw  = tid >> 4;
    const int l16 = tid & 15;

    // qbar[d] = sum_f fs[f] * q[b,f,d]
    {
        const float4* qb4 = (const float4*)(q + (size_t)b * FF * DD);
        float4 a = make_float4(0.f, 0.f, 0.f, 0.f);
#pragma unroll
        for (int fi = 0; fi < 4; ++fi) {
            int f = hw + 16 * fi;
            float s = fs[f];
            float4 v = qb4[f * 16 + l16];
            a.x += s * v.x; a.y += s * v.y; a.z += s * v.z; a.w += s * v.w;
        }
        ((float4*)spart)[hw * 16 + l16] = a;
    }
    __syncthreads();
    if (tid < DD) {
        float s = 0.f;
#pragma unroll
        for (int i = 0; i < 16; ++i) s += spart[i * DD + tid];
        squ[tid] = s;
    }
    __syncthreads();

    // tmp[e] = sum_c qbar[c] * Wq[c,e]
    {
        float4 a = make_float4(0.f, 0.f, 0.f, 0.f);
#pragma unroll
        for (int ci = 0; ci < 4; ++ci) {
            int c = hw * 4 + ci;
            float s = squ[c];
            float4 v = ((const float4*)Wq)[c * 16 + l16];
            a.x += s * v.x; a.y += s * v.y; a.z += s * v.z; a.w += s * v.w;
        }
        ((float4*)spart)[hw * 16 + l16] = a;
    }
    __syncthreads();
    if (tid < DD) {
        float s = 0.f;
#pragma unroll
        for (int i = 0; i < 16; ++i) s += spart[i * DD + tid];
        stmp[tid] = s;
    }
    __syncthreads();

    // u[row] = sum_e tmp[e] * Wk[row,e]
    {
        float4 tv = ((const float4*)stmp)[l16];
#pragma unroll
        for (int r = 0; r < 4; ++r) {
            int row = hw + 16 * r;
            float4 wv = ((const float4*)(Wk + row * DD))[l16];
            float p = wv.x * tv.x + wv.y * tv.y + wv.z * tv.z + wv.w * tv.w;
#pragma unroll
            for (int o = 8; o; o >>= 1)
                p += __shfl_xor_sync(0xffffffffu, p, o);
            if (l16 == 0) g_u[b * DD + row] = p;
        }
    }
}

// ==== Kernel 2: 4-chunk pipelined DMA (all issued up-front) + fused pass ====
__global__ __launch_bounds__(NT, 4)
void score_kernel(const float* __restrict__ k,
                  const int*   __restrict__ kes_length,
                  const float* __restrict__ bias,
                  const float* __restrict__ Wv,
                  float*       __restrict__ out) {
    extern __shared__ float smd[];
    float* kbuf  = smd;                    // 12800 floats : k tile
    float* spart = kbuf + KT;              // 16*64 partials
    float* su    = spart + 16 * DD;        // w
    float* sub   = su + DD;                // u (staged from g_u)
    float* swr   = sub + DD;               // 16 exp-sums

    const int b    = blockIdx.x;
    const int tid  = threadIdx.x;
    const int hw   = tid >> 4;             // half-warp id 0..15
    const int l16  = tid & 15;

    // ---- issue ALL 4 chunk DMAs immediately, separate commit groups ----
    {
        const uint32_t sbk = (uint32_t)__cvta_generic_to_shared(kbuf);
        const char* gk = (const char*)(k + (size_t)b * KT);
#pragma unroll
        for (int c = 0; c < 4; ++c) {
            const uint32_t so = sbk + c * (CHU * 16);
            const char*    go = gk + (size_t)c * (CHU * 16);
#pragma unroll
            for (int r = 0; r < 3; ++r) {
                int u = tid + r * NT;
                cp_async16(so + u * 16, go + (size_t)u * 16);
            }
            if (tid < CHU - 3 * NT)        // 800 - 768 = 32 remainder
                cp_async16(so + (tid + 3 * NT) * 16, go + (size_t)(tid + 3 * NT) * 16);
            cp_commit();
        }
    }

    // tiny loads ride under the DMA
    if (tid < 16)
        ((float4*)sub)[tid] = ((const float4*)(g_u + (size_t)b * DD))[tid];
    const int   len   = kes_length[b];
    const float biasD = bias[0] * (float)DD;
    const float mfill = (len == 0) ? 1.f : 0.f;
    __syncthreads();                        // sub visible to all
    const float4 uv = ((const float4*)sub)[l16];

    // ---- fused score+weighted pass, chunk by chunk as DMA lands ----
    float4 wa   = make_float4(0.f, 0.f, 0.f, 0.f);
    float  esum = 0.f;

#pragma unroll
    for (int c = 0; c < 4; ++c) {
        if      (c == 0) cp_wait<3>();
        else if (c == 1) cp_wait<2>();
        else if (c == 2) cp_wait<1>();
        else             cp_wait<0>();
        __syncthreads();                    // make chunk c visible to all threads

#pragma unroll
        for (int i = 0; i < 4; ++i) {
            int rl = hw + 16 * i;           // row within chunk
            if (rl < CH) {
                int t = c * CH + rl;
                float4 kv = *(const float4*)(kbuf + t * 64 + (l16 << 2));
                float p = kv.x * uv.x + kv.y * uv.y + kv.z * uv.z + kv.w * uv.w;
#pragma unroll
                for (int o = 8; o; o >>= 1)
                    p += __shfl_xor_sync(0xffffffffu, p, o);   // 16-lane reduce
                float e = (t < len) ? fast_exp8(fast_sigmoid(p + biasD)) : mfill;
                wa.x += e * kv.x; wa.y += e * kv.y;
                wa.z += e * kv.z; wa.w += e * kv.w;
                esum += e;
            }
        }
    }

    ((float4*)spart)[hw * 16 + l16] = wa;
    if (l16 == 0) swr[hw] = esum;
    __syncthreads();

    if (tid < DD) {
        float s = 0.f;
#pragma unroll
        for (int i = 0; i < 16; ++i) s += spart[i * DD + tid];
        su[tid] = s;
    }
    __syncthreads();

    // ---- out[b,e] = inv * sum_c w[c] * Wv[c,e] ----
    {
        float4 a = make_float4(0.f, 0.f, 0.f, 0.f);
#pragma unroll
        for (int ci = 0; ci < 4; ++ci) {
            int c = hw * 4 + ci;
            float s = su[c];
            float4 v = ((const float4*)Wv)[c * 16 + l16];
            a.x += s * v.x; a.y += s * v.y; a.z += s * v.z; a.w += s * v.w;
        }
        ((float4*)spart)[hw * 16 + l16] = a;
    }
    __syncthreads();
    if (tid < DD) {
        float tot = 0.f;
#pragma unroll
        for (int i = 0; i < 16; ++i) tot += swr[i];
        float s = 0.f;
#pragma unroll
        for (int i = 0; i < 16; ++i) s += spart[i * DD + tid];
        out[(size_t)b * DD + tid] = s * (1.f / tot);
    }
}

extern "C" void kernel_launch(void* const* d_in, const int* in_sizes, int n_in,
                              void* d_out, int out_size) {
    const float* q    = (const float*)d_in[0];
    const float* k    = (const float*)d_in[1];
    // d_in[2] = v : unused by the reference computation
    const int*   kes  = (const int*)  d_in[3];
    const float* fs   = (const float*)d_in[4];
    const float* bias = (const float*)d_in[5];
    const float* Wq   = (const float*)d_in[6];
    const float* Wk   = (const float*)d_in[7];
    const float* Wv   = (const float*)d_in[8];
    float*       out  = (float*)d_out;

    cudaFuncSetAttribute(score_kernel, cudaFuncAttributePreferredSharedMemoryCarveout, 100);
    cudaFuncSetAttribute(score_kernel, cudaFuncAttributeMaxDynamicSharedMemorySize, SMEM2_BYTES);

    u_kernel<<<BB, NT>>>(q, fs, Wq, Wk);
    score_kernel<<<BB, NT, SMEM2_BYTES>>>(k, kes, bias, Wv, out);
}